// round 4
// baseline (speedup 1.0000x reference)
#include <cuda_runtime.h>

#define H 8192
#define W 8192
#define KH 7
#define KW 7
#define OH (H - KH + 1)   // 8186
#define OW (W - KW + 1)   // 8186

#define TPB    128
#define CPT    4                     // cols per thread (2 f32x2 pairs)
#define RPT    8                     // rows per thread
#define TILE_X (32 * CPT)            // 128
#define TILE_Y (4 * RPT)             // 32
#define SM_H   (TILE_Y + KH - 1)     // 38
#define SM_W   (TILE_X + KW - 1)     // 134
#define SP     136                   // pitch: 544B, 16B-aligned rows
#define VLEN   (RPT + KH - 1)        // 14

typedef unsigned long long u64;

__device__ __forceinline__ u64 fma2(u64 a, u64 b, u64 c) {
    u64 d;
    asm("fma.rn.f32x2 %0, %1, %2, %3;" : "=l"(d) : "l"(a), "l"(b), "l"(c));
    return d;
}
__device__ __forceinline__ u64 splat2(float w) {
    u64 d;
    asm("mov.b64 %0, {%1, %1};" : "=l"(d) : "f"(w));
    return d;
}
// {hi(a), lo(b)} — register-only, no L1 bytes
__device__ __forceinline__ u64 crossing(u64 a, u64 b) {
    u64 r;
    asm("{\n\t.reg .b32 al, ah, bl, bh;\n\t"
        "mov.b64 {al, ah}, %1;\n\t"
        "mov.b64 {bl, bh}, %2;\n\t"
        "mov.b64 %0, {ah, bl};\n\t}"
        : "=l"(r) : "l"(a), "l"(b));
    return r;
}

__global__ __launch_bounds__(TPB, 3)
void conv7x7_rot_kernel(const float* __restrict__ x,
                        const float* __restrict__ wgt,
                        const float* __restrict__ bias,
                        float* __restrict__ out)
{
    __shared__ __align__(16) float tile[SM_H * SP];

    const int tid  = threadIdx.x;
    const int col0 = blockIdx.x * TILE_X;
    const int row0 = blockIdx.y * TILE_Y;

    // ---- All 49 weights as f32x2 splats in registers ----
    u64 w2[KH * KW];
#pragma unroll
    for (int i = 0; i < KH * KW; i++) w2[i] = splat2(__ldg(&wgt[i]));

    // ---- Tile fill: 38 rows x 134 cols, clamped (single copy) ----
    {
        const int gc0 = min(col0 + tid, W - 1);
        const int gc1 = min(col0 + 128 + tid, W - 1);
#pragma unroll 2
        for (int r = 0; r < SM_H; r++) {
            const int gr = min(row0 + r, H - 1);
            const float* xr = x + (size_t)gr * W;
            tile[r * SP + tid] = __ldg(&xr[gc0]);
            if (tid < SM_W - 128) tile[r * SP + 128 + tid] = __ldg(&xr[gc1]);
        }
    }
    __syncthreads();

    // ---- Row-rotation compute: each input row loaded ONCE ----
    const int lane  = tid & 31;
    const int rbase = (tid >> 5) * RPT;   // 0,8,16,24
    const int cb    = lane * CPT;         // 0..124, 16B-aligned in smem

    u64 acc0[RPT], acc1[RPT];
#pragma unroll
    for (int o = 0; o < RPT; o++) { acc0[o] = 0ULL; acc1[o] = 0ULL; }

#pragma unroll
    for (int t = 0; t < VLEN; t++) {
        const u64* b64 = (const u64*)&tile[(rbase + t) * SP + cb];
        u64 P0, P1, P2, P3, P4;
        { ulonglong2 a = *(const ulonglong2*)(b64);     P0 = a.x; P1 = a.y; }
        { ulonglong2 a = *(const ulonglong2*)(b64 + 2); P2 = a.x; P3 = a.y; }
        P4 = b64[4];

        const u64 X1 = crossing(P0, P1);
        const u64 X3 = crossing(P1, P2);
        const u64 X5 = crossing(P2, P3);
        const u64 X7 = crossing(P3, P4);

        const u64 pr0[KW] = { P0, X1, P1, X3, P2, X5, P3 };
        const u64 pr1[KW] = { P1, X3, P2, X5, P3, X7, P4 };

#pragma unroll
        for (int kr = 0; kr < KH; kr++) {
            const int o = t - kr;
            if (o >= 0 && o < RPT) {
#pragma unroll
                for (int kc = 0; kc < KW; kc++) {
                    acc0[o] = fma2(pr0[kc], w2[kr * KW + kc], acc0[o]);
                    acc1[o] = fma2(pr1[kc], w2[kr * KW + kc], acc1[o]);
                }
            }
        }
    }

    // ---- Epilogue: bias + guarded STG.64 (pairs never straddle, OW even) ----
    const u64 b2 = splat2(__ldg(&bias[0]));
    const int ocol = col0 + cb;
#pragma unroll
    for (int o = 0; o < RPT; o++) {
        const int orow = row0 + rbase + o;
        if (orow < OH) {
            float* orw = out + (size_t)orow * OW;
            if (ocol < OW) {
                u64 r;
                asm("add.rn.f32x2 %0, %1, %2;" : "=l"(r) : "l"(acc0[o]), "l"(b2));
                *(u64*)&orw[ocol] = r;
            }
            if (ocol + 2 < OW) {
                u64 r;
                asm("add.rn.f32x2 %0, %1, %2;" : "=l"(r) : "l"(acc1[o]), "l"(b2));
                *(u64*)&orw[ocol + 2] = r;
            }
        }
    }
}

extern "C" void kernel_launch(void* const* d_in, const int* in_sizes, int n_in,
                              void* d_out, int out_size)
{
    const float* x    = (const float*)d_in[0];
    const float* wgt  = (const float*)d_in[1];
    const float* bias = (const float*)d_in[2];
    float* out        = (float*)d_out;

    dim3 block(TPB, 1, 1);
    dim3 grid((OW + TILE_X - 1) / TILE_X, (OH + TILE_Y - 1) / TILE_Y, 1);
    conv7x7_rot_kernel<<<grid, block>>>(x, wgt, bias, out);
}

// round 5
// speedup vs baseline: 2.6020x; 2.6020x over previous
#include <cuda_runtime.h>

#define H 8192
#define W 8192
#define KH 7
#define KW 7
#define OH (H - KH + 1)   // 8186
#define OW (W - KW + 1)   // 8186

#define TPB    128
#define RPT    16                    // rows per thread
#define TILE_X 64                    // 32 lanes * 2 cols (one f32x2 pair)
#define TILE_Y 64                    // 4 warps * 16 rows
#define SM_H   (TILE_Y + KH - 1)     // 70
#define SM_W   (TILE_X + KW - 1)     // 70
#define SP     72                    // smem pitch (floats)
#define VLEN   (RPT + KH - 1)        // 22

typedef unsigned long long u64;

__device__ __forceinline__ u64 fma2(u64 a, u64 b, u64 c) {
    u64 d;
    asm("fma.rn.f32x2 %0, %1, %2, %3;" : "=l"(d) : "l"(a), "l"(b), "l"(c));
    return d;
}
__device__ __forceinline__ u64 splat2(float w) {
    u64 d;
    asm("mov.b64 %0, {%1, %1};" : "=l"(d) : "f"(w));
    return d;
}
// {hi(a), lo(b)} — register MOVs only, zero L1 bytes
__device__ __forceinline__ u64 crossing(u64 a, u64 b) {
    u64 r;
    asm("{\n\t.reg .b32 al, ah, bl, bh;\n\t"
        "mov.b64 {al, ah}, %1;\n\t"
        "mov.b64 {bl, bh}, %2;\n\t"
        "mov.b64 %0, {ah, bl};\n\t}"
        : "=l"(r) : "l"(a), "l"(b));
    return r;
}

__global__ __launch_bounds__(TPB)
void conv7x7_rot2_kernel(const float* __restrict__ x,
                         const float* __restrict__ wgt,
                         const float* __restrict__ bias,
                         float* __restrict__ out)
{
    __shared__ __align__(16) float tile[SM_H * SP];

    const int tid  = threadIdx.x;
    const int col0 = blockIdx.x * TILE_X;
    const int row0 = blockIdx.y * TILE_Y;

    // ---- Tile fill: 70x70, clamped reads ----
    for (int idx = tid; idx < SM_H * SM_W; idx += TPB) {
        const int r = idx / SM_W;             // const divisor -> mul/shift
        const int c = idx - r * SM_W;
        const int gr = min(row0 + r, H - 1);
        const int gc = min(col0 + c, W - 1);
        tile[r * SP + c] = __ldg(&x[(size_t)gr * W + gc]);
    }

    // ---- All 49 weights as f32x2 splats (fits: ~155 regs, no cap) ----
    u64 w2[KH * KW];
#pragma unroll
    for (int i = 0; i < KH * KW; i++) w2[i] = splat2(__ldg(&wgt[i]));

    __syncthreads();

    const int lane  = tid & 31;
    const int rbase = (tid >> 5) * RPT;       // 0,16,32,48
    const int cb    = lane * 2;               // 0..62 (u64-aligned)

    u64 acc[RPT];
#pragma unroll
    for (int o = 0; o < RPT; o++) acc[o] = 0ULL;

    const float* base = &tile[rbase * SP + cb];

    // ---- Row rotation: each input row read ONCE (4x LDS.64 = 32B),
    //      then all applicable (kr,kc) weights applied ----
#pragma unroll
    for (int t = 0; t < VLEN; t++) {
        const u64* p = (const u64*)(base + t * SP);
        const u64 P0 = p[0];                  // cols {0,1}
        const u64 P2 = p[1];                  // cols {2,3}
        const u64 P4 = p[2];                  // cols {4,5}
        const u64 P6 = p[3];                  // cols {6,7}
        const u64 X1 = crossing(P0, P2);      // cols {1,2}
        const u64 X3 = crossing(P2, P4);      // cols {3,4}
        const u64 X5 = crossing(P4, P6);      // cols {5,6}

#pragma unroll
        for (int kr = 0; kr < KH; kr++) {
            const int o = t - kr;             // compile-time constant per (t,kr)
            if (o >= 0 && o < RPT) {
                u64 a = acc[o];
                a = fma2(P0, w2[kr * KW + 0], a);
                a = fma2(X1, w2[kr * KW + 1], a);
                a = fma2(P2, w2[kr * KW + 2], a);
                a = fma2(X3, w2[kr * KW + 3], a);
                a = fma2(P4, w2[kr * KW + 4], a);
                a = fma2(X5, w2[kr * KW + 5], a);
                a = fma2(P6, w2[kr * KW + 6], a);
                acc[o] = a;
            }
        }
    }

    // ---- Epilogue: bias + STG.64 (OW even: pairs never straddle) ----
    const u64 b2 = splat2(__ldg(&bias[0]));
    const int ocol = col0 + cb;
    if (ocol < OW) {
#pragma unroll
        for (int o = 0; o < RPT; o++) {
            const int orow = row0 + rbase + o;
            if (orow < OH) {
                u64 r;
                asm("add.rn.f32x2 %0, %1, %2;" : "=l"(r) : "l"(acc[o]), "l"(b2));
                *(u64*)&out[(size_t)orow * OW + ocol] = r;
            }
        }
    }
}

extern "C" void kernel_launch(void* const* d_in, const int* in_sizes, int n_in,
                              void* d_out, int out_size)
{
    const float* x    = (const float*)d_in[0];
    const float* wgt  = (const float*)d_in[1];
    const float* bias = (const float*)d_in[2];
    float* out        = (float*)d_out;

    dim3 block(TPB, 1, 1);
    dim3 grid((OW + TILE_X - 1) / TILE_X, (OH + TILE_Y - 1) / TILE_Y, 1);
    conv7x7_rot2_kernel<<<grid, block>>>(x, wgt, bias, out);
}